// round 2
// baseline (speedup 1.0000x reference)
#include <cuda_runtime.h>
#include <cstdint>

namespace {
constexpr int L2C  = 65536;
constexpr int NC   = 2 * L2C;     // 131072
constexpr int FINC = 8;
constexpr int FOUTC= 8;
constexpr int KC   = 13;
constexpr int IK   = FINC * KC;   // 104
constexpr int EPB  = 32;          // edges per block
constexpr int TPB  = 256;         // EPB * FOUTC
constexpr int PAD  = 108;         // row pad in floats (multiple of 4 for float4)
}

// Scratch: x transposed to (N, FIN) so one gather = one 32B sector.
__device__ __align__(16) float g_xt[(size_t)NC * FINC];
// 1 => masks are 1-byte elements; 0 => masks are 4-byte words ({0,1} int32 or {0,1.0f} float32)
__device__ int g_mask_is_byte;

__global__ void detect_kernel(const uint32_t* __restrict__ M) {
    int bad = 0;
    for (int i = threadIdx.x; i < 1024; i += 32) {
        uint32_t w = M[i];
        if (!(w == 0u || w == 1u || w == 0x3f800000u)) bad = 1;
    }
    bad = __any_sync(0xffffffffu, bad);
    if (threadIdx.x == 0) g_mask_is_byte = bad;
}

__global__ __launch_bounds__(TPB) void transpose_kernel(const float* __restrict__ x) {
    int j = blockIdx.x * blockDim.x + threadIdx.x;
    if (j >= NC) return;
    float4 a, b;
    a.x = x[0 * NC + j]; a.y = x[1 * NC + j]; a.z = x[2 * NC + j]; a.w = x[3 * NC + j];
    b.x = x[4 * NC + j]; b.y = x[5 * NC + j]; b.z = x[6 * NC + j]; b.w = x[7 * NC + j];
    float4* dst = reinterpret_cast<float4*>(g_xt) + (size_t)j * 2;
    dst[0] = a;
    dst[1] = b;
}

__global__ __launch_bounds__(TPB) void edge_kernel(
    const float* __restrict__ Wh, const float* __restrict__ Wv,
    const float* __restrict__ bh, const float* __restrict__ bv,
    const uint8_t* __restrict__ Mh, const uint8_t* __restrict__ Mv,
    const int* __restrict__ Kh, const int* __restrict__ Kv,
    const int* __restrict__ ELh, const int* __restrict__ ELv,
    float* __restrict__ out)
{
    const bool vert = (blockIdx.y != 0);
    const float*   W    = vert ? Wv  : Wh;
    const float*   bias = vert ? bv  : bh;
    const uint8_t* M    = vert ? Mv  : Mh;
    const int*     KER  = vert ? Kv  : Kh;
    const int*     EL   = vert ? ELv : ELh;

    __shared__ float Ws[FOUTC * PAD];
    __shared__ float xs[EPB * PAD];
    __shared__ int   kers[EPB * KC];
    __shared__ float bs[FOUTC];

    const int tid = threadIdx.x;
    const int e0  = blockIdx.x * EPB;

    for (int t = tid; t < FOUTC * IK; t += TPB)
        Ws[(t / IK) * PAD + (t % IK)] = W[t];
    if (tid < FOUTC) bs[tid] = bias[tid];
    for (int t = tid; t < EPB * KC; t += TPB)
        kers[t] = KER[e0 * KC + t];
    __syncthreads();

    const int el = tid >> 3;   // local edge 0..31
    const int o  = tid & 7;    // output feature 0..7

    // Cooperative gather: thread (el,o) supplies feature row i=o for its edge.
    #pragma unroll
    for (int k = 0; k < KC; k++) {
        int j = kers[el * KC + k];
        xs[el * PAD + o * KC + k] = g_xt[(size_t)j * FINC + o];
    }
    __syncthreads();

    float acc = bs[o];
    const float4* Wr = reinterpret_cast<const float4*>(Ws + o * PAD);
    const float4* xr = reinterpret_cast<const float4*>(xs + el * PAD);

    if (g_mask_is_byte) {
        // masks: 1 byte per element
        const uint2* mp = reinterpret_cast<const uint2*>(
            M + (size_t)(e0 + el) * (FOUTC * IK) + (size_t)o * IK);
        #pragma unroll
        for (int q = 0; q < IK / 4; q++) {
            uint2 mw = mp[q >> 1];
            uint32_t m = (q & 1) ? mw.y : mw.x;
            float4 wv = Wr[q];
            float4 xv = xr[q];
            if (m & 0x000000ffu) acc = fmaf(wv.x, xv.x, acc);
            if (m & 0x0000ff00u) acc = fmaf(wv.y, xv.y, acc);
            if (m & 0x00ff0000u) acc = fmaf(wv.z, xv.z, acc);
            if (m & 0xff000000u) acc = fmaf(wv.w, xv.w, acc);
        }
    } else {
        // masks: 4 bytes per element ({0,1} int32 or {0.0f,1.0f} float32) — nonzero test works for both
        const uint4* mp4 = reinterpret_cast<const uint4*>(
            reinterpret_cast<const uint32_t*>(M) +
            (size_t)(e0 + el) * (FOUTC * IK) + (size_t)o * IK);
        #pragma unroll
        for (int q = 0; q < IK / 4; q++) {
            uint4 m = mp4[q];
            float4 wv = Wr[q];
            float4 xv = xr[q];
            if (m.x) acc = fmaf(wv.x, xv.x, acc);
            if (m.y) acc = fmaf(wv.y, xv.y, acc);
            if (m.z) acc = fmaf(wv.z, xv.z, acc);
            if (m.w) acc = fmaf(wv.w, xv.w, acc);
        }
    }

    const float SCALE = (float)((2.0 + 2.0 * 2.718281828459045235) /
                                (2.718281828459045235 - 1.0));
    float s   = 1.0f / (1.0f + __expf(-acc));
    float res = (s - 0.5f) * SCALE;

    int col = EL[e0 + el];
    out[(size_t)o * NC + col] = res;
}

extern "C" void kernel_launch(void* const* d_in, const int* in_sizes, int n_in,
                              void* d_out, int out_size) {
    const float*   x   = (const float*)  d_in[0];
    const float*   Wh  = (const float*)  d_in[1];
    const float*   Wv  = (const float*)  d_in[2];
    const float*   bh  = (const float*)  d_in[3];
    const float*   bv  = (const float*)  d_in[4];
    const uint8_t* Mh  = (const uint8_t*)d_in[5];
    const uint8_t* Mv  = (const uint8_t*)d_in[6];
    const int*     Kh  = (const int*)    d_in[7];
    const int*     Kv  = (const int*)    d_in[8];
    const int*     ELh = (const int*)    d_in[9];
    const int*     ELv = (const int*)    d_in[10];
    float* out = (float*)d_out;

    detect_kernel<<<1, 32>>>((const uint32_t*)Mh);
    transpose_kernel<<<NC / TPB, TPB>>>(x);

    dim3 grid(L2C / EPB, 2);   // y=0 horizontal branch, y=1 vertical
    edge_kernel<<<grid, TPB>>>(Wh, Wv, bh, bv, Mh, Mv, Kh, Kv, ELh, ELv, out);
}